// round 9
// baseline (speedup 1.0000x reference)
#include <cuda_runtime.h>

// ============================================================================
// Convert2ImageLayer: out[b,h,w,:] = feat[b, slic[b,h,w]-1, :]  (0 if invalid)
// Shapes: B=8, N=1024, C=128, H=W=512.
//
// R9 probe: 256-bit loads/stores (PTX ISA 8.7, sm_100+). Same warp/pixel
// mapping as the measured-optimal P=4 kernel, but each lane moves a 32B chunk
// (16 lanes cover one 512B feature row), so the warp covers 2 pixels per
// memory instruction: 2x LDG.256 gathers + 2x coalesced 1KB STG.256 bursts.
// Halves L1tex instruction/wavefront issue at identical DRAM traffic and
// identical bytes-in-flight MLP.
// ============================================================================

static constexpr int  Nc = 1024;
static constexpr int  Cf = 128;           // floats per pixel row
static constexpr int  HW_SHIFT = 18;      // H*W = 2^18 pixels per batch image
static constexpr long long PIX = 8LL << HW_SHIFT;   // 2,097,152 pixels
static constexpr int  P = 4;              // pixels per warp

__device__ __forceinline__ void ldg256(const float* __restrict__ p, float r[8]) {
    asm volatile("ld.global.v8.f32 {%0,%1,%2,%3,%4,%5,%6,%7}, [%8];"
                 : "=f"(r[0]), "=f"(r[1]), "=f"(r[2]), "=f"(r[3]),
                   "=f"(r[4]), "=f"(r[5]), "=f"(r[6]), "=f"(r[7])
                 : "l"(p));
}

__device__ __forceinline__ void stg256_cs(float* __restrict__ p, const float r[8]) {
    asm volatile("st.global.cs.v8.f32 [%0], {%1,%2,%3,%4,%5,%6,%7,%8};"
                 :: "l"(p),
                    "f"(r[0]), "f"(r[1]), "f"(r[2]), "f"(r[3]),
                    "f"(r[4]), "f"(r[5]), "f"(r[6]), "f"(r[7])
                 : "memory");
}

__global__ void __launch_bounds__(256)
convert2image_gather_v8(const float* __restrict__ feat,   // [B, N, C]
                        const int*   __restrict__ slic,   // [B*H*W]
                        float*       __restrict__ out)    // [B*H*W, C]
{
    const long long warp_gid = (long long)blockIdx.x * (blockDim.x >> 5)
                             + (threadIdx.x >> 5);
    const long long pix0 = warp_gid * P;
    const int lane = threadIdx.x & 31;
    const int half = lane >> 4;            // which pixel of the pair
    const int c8   = lane & 15;            // which 32B chunk of the 512B row

    if (pix0 >= PIX) return;

    // All P pixels of a warp lie in the same batch image (P divides H*W).
    const int b = (int)(pix0 >> HW_SHIFT);
    const float* __restrict__ fb = feat + ((long long)b * Nc) * Cf;

    // Lanes 0..P-1 fetch the P segment labels (one 16B sector total).
    int myidx = 0;
    if (lane < P) myidx = __ldg(slic + pix0 + lane) - 1;   // labels 1-indexed

    // Two independent 256-bit gathers (pixels {0,1} and {2,3} of the quad).
    float v[2][8];
    #pragma unroll
    for (int j = 0; j < 2; j++) {
        const int idx = __shfl_sync(0xffffffffu, myidx, 2 * j + half);
        #pragma unroll
        for (int k = 0; k < 8; k++) v[j][k] = 0.f;
        if ((unsigned)idx < (unsigned)Nc) {
            ldg256(fb + (long long)idx * Cf + c8 * 8, v[j]);
        }
    }

    // Two coalesced 1KB streaming store bursts (write-once, evict-first).
    float* __restrict__ o = out + (pix0 << 7) + (long long)half * Cf + c8 * 8;
    #pragma unroll
    for (int j = 0; j < 2; j++) {
        stg256_cs(o + (long long)(2 * j) * Cf, v[j]);
    }
}

extern "C" void kernel_launch(void* const* d_in, const int* in_sizes, int n_in,
                              void* d_out, int out_size)
{
    const float* feat = (const float*)d_in[0];   // graph_lstm_output fp32 [B,N,C]
    const int*   slic = (const int*)d_in[1];     // slic_output int32 [B,H,W,1]
    float*       out  = (float*)d_out;           // fp32 [B,H,W,C]

    const int threads = 256;                      // 8 warps -> 32 pixels/block
    const long long pixels_per_block = (threads / 32) * P;
    const unsigned blocks = (unsigned)((PIX + pixels_per_block - 1) / pixels_per_block); // 65,536

    convert2image_gather_v8<<<blocks, threads>>>(feat, slic, out);
}